// round 2
// baseline (speedup 1.0000x reference)
#include <cuda_runtime.h>
#include <cuda_bf16.h>
#include <cstdint>

// ---------------------------------------------------------------------------
// Binarized MLP: x[16384,784] -> 3x (binlinear + BN + ReLU) -> binlinear + sigmoid
// Numeric strategy: activations split into hi/lo bf16 halves, K-concatenated;
// sign weights duplicated along K; mma.sync bf16 GEMM with fp32 accumulate
// reproduces fp32-level accuracy (residual ~2^-17).
// NOTE: harness emits compute_100 PTX (no 'a' feature) -> tcgen05 unavailable;
// mma.sync.m16n8k16 is the fastest legal tensor path.
// ---------------------------------------------------------------------------

#define BATCH 16384

// Device-global scratch (cudaMalloc is forbidden)
__device__ __nv_bfloat16 g_act[(size_t)BATCH * 2048];   // hi/lo activations
__device__ __nv_bfloat16 g_wcat[(size_t)1024 * 2048];   // duplicated sign weights
__device__ float         g_h[(size_t)BATCH * 1024];     // pre-BN GEMM output
__device__ float         g_sum[1024];
__device__ float         g_sumsq[1024];

// ---------------------------------------------------------------------------
// PTX helpers (baseline sm_80/90 PTX only — no 'a'-gated instructions)
// ---------------------------------------------------------------------------
__device__ __forceinline__ uint32_t smem_u32(const void* p) {
    uint32_t a;
    asm("{ .reg .u64 t; cvta.to.shared.u64 t, %1; cvt.u32.u64 %0, t; }"
        : "=r"(a) : "l"(p));
    return a;
}

__device__ __forceinline__ void cp16(uint32_t dst, const void* src) {
    asm volatile("cp.async.cg.shared.global [%0], [%1], 16;"
                 :: "r"(dst), "l"(src) : "memory");
}
__device__ __forceinline__ void cp_commit() {
    asm volatile("cp.async.commit_group;" ::: "memory");
}

__device__ __forceinline__ void ldmx4(uint32_t* r, uint32_t addr) {
    asm volatile("ldmatrix.sync.aligned.m8n8.x4.shared.b16 {%0,%1,%2,%3}, [%4];"
                 : "=r"(r[0]), "=r"(r[1]), "=r"(r[2]), "=r"(r[3]) : "r"(addr));
}

__device__ __forceinline__ void mma16816(float* c, const uint32_t* a, const uint32_t* b) {
    asm volatile(
        "mma.sync.aligned.m16n8k16.row.col.f32.bf16.bf16.f32 "
        "{%0,%1,%2,%3}, {%4,%5,%6,%7}, {%8,%9}, {%0,%1,%2,%3};"
        : "+f"(c[0]), "+f"(c[1]), "+f"(c[2]), "+f"(c[3])
        : "r"(a[0]), "r"(a[1]), "r"(a[2]), "r"(a[3]), "r"(b[0]), "r"(b[1]));
}

// ---------------------------------------------------------------------------
// Prep kernels
// ---------------------------------------------------------------------------
__global__ void prep_x_kernel(const float* __restrict__ x) {
    int idx = blockIdx.x * 256 + threadIdx.x;        // total 16384*1600
    int k = idx % 1600;
    int r = idx / 1600;
    __nv_bfloat16 v;
    if (k < 784) {
        v = __float2bfloat16(x[(size_t)r * 784 + k]);
    } else if (k < 1568) {
        float xv = x[(size_t)r * 784 + (k - 784)];
        float hi = __bfloat162float(__float2bfloat16(xv));
        v = __float2bfloat16(xv - hi);
    } else {
        v = __float2bfloat16(0.0f);
    }
    g_act[(size_t)r * 1600 + k] = v;
}

// wcat[n, k] = wcat[n, K+k] = sign(w[n,k]); pad zeros to stride
__global__ void binarize_kernel(const float* __restrict__ w, int K, int stride) {
    int idx = blockIdx.x * 256 + threadIdx.x;
    int k = idx % stride;
    int n = idx / stride;
    float s = 0.0f;
    if (k < 2 * K) {
        int kk = (k < K) ? k : (k - K);
        s = (w[(size_t)n * K + kk] >= 0.0f) ? 1.0f : -1.0f;
    }
    g_wcat[(size_t)n * stride + k] = __float2bfloat16(s);
}

// ---------------------------------------------------------------------------
// mma.sync GEMM: g_h[16384,1024] = g_act[16384,lda] @ g_wcat[1024,lda]^T
// CTA tile 128x128x64, 8 warps (2x4), warp tile 64x32, 3-stage cp.async.
// SMEM: SW128 swizzle, 128B rows, A(16KB)+B(16KB) per stage, 3 stages = 96KB.
// ---------------------------------------------------------------------------
#define GEMM_SMEM (3 * 32768)

__global__ __launch_bounds__(256, 2) void gemm_kernel(int lda, int KT) {
    extern __shared__ char smem[];
    uint32_t sb = smem_u32(smem);
    int tid = threadIdx.x, lane = tid & 31, warp = tid >> 5;
    int wm = (warp & 1) * 64;       // warp M offset within CTA tile
    int wn = (warp >> 1) * 32;      // warp N offset
    int m0 = blockIdx.x * 128, n0 = blockIdx.y * 128;
    const __nv_bfloat16* A = g_act;
    const __nv_bfloat16* W = g_wcat;

    auto load_stage = [&](int s, int kt) {
        uint32_t baseA = sb + (uint32_t)s * 32768u;
        uint32_t baseB = baseA + 16384u;
        const __nv_bfloat16* Ap = A + (size_t)m0 * lda + kt * 64;
        const __nv_bfloat16* Wp = W + (size_t)n0 * lda + kt * 64;
#pragma unroll
        for (int i = 0; i < 4; i++) {
            int idx = tid + i * 256;                 // 1024 chunks each
            int row = idx >> 3, ck = idx & 7;
            uint32_t sw = (uint32_t)(row * 128 + ((ck ^ (row & 7)) << 4));
            cp16(baseA + sw, Ap + (size_t)row * lda + ck * 8);
            cp16(baseB + sw, Wp + (size_t)row * lda + ck * 8);
        }
        cp_commit();
    };

    load_stage(0, 0);
    load_stage(1, 1);

    float acc[4][4][4];
#pragma unroll
    for (int mm = 0; mm < 4; mm++)
#pragma unroll
        for (int nn = 0; nn < 4; nn++)
#pragma unroll
            for (int q = 0; q < 4; q++) acc[mm][nn][q] = 0.0f;

    // per-lane fragment row indices (fixed)
    int rA = wm + (lane & 15);                       // A ldmatrix row
    int rB = wn + ((lane >> 4) << 3) + (lane & 7);   // B ldmatrix row (x4 = 2 n-blocks)
    int ckA_lo = (lane >> 4);                        // A chunk low bit
    int ckB_lo = ((lane >> 3) & 1);                  // B chunk low bit

    for (int kt = 0; kt < KT; kt++) {
        if (kt == KT - 1) asm volatile("cp.async.wait_group 0;" ::: "memory");
        else              asm volatile("cp.async.wait_group 1;" ::: "memory");
        __syncthreads();
        if (kt + 2 < KT) load_stage((kt + 2) % 3, kt + 2);

        uint32_t baseA = sb + (uint32_t)(kt % 3) * 32768u;
        uint32_t baseB = baseA + 16384u;

#pragma unroll
        for (int kk = 0; kk < 4; kk++) {
            uint32_t aF[4][4], bF[4][2];
            int ckA = kk * 2 + ckA_lo;
            int ckB = kk * 2 + ckB_lo;
#pragma unroll
            for (int mm = 0; mm < 4; mm++) {
                int row = rA + mm * 16;
                ldmx4(aF[mm], baseA + row * 128 + ((ckA ^ (row & 7)) << 4));
            }
#pragma unroll
            for (int p = 0; p < 2; p++) {
                int row = rB + p * 16;
                uint32_t r[4];
                ldmx4(r, baseB + row * 128 + ((ckB ^ (row & 7)) << 4));
                bF[p * 2][0] = r[0]; bF[p * 2][1] = r[1];
                bF[p * 2 + 1][0] = r[2]; bF[p * 2 + 1][1] = r[3];
            }
#pragma unroll
            for (int mm = 0; mm < 4; mm++)
#pragma unroll
                for (int nn = 0; nn < 4; nn++)
                    mma16816(acc[mm][nn], aF[mm], bF[nn]);
        }
    }

    // Epilogue: direct register -> gmem (float2 per half-fragment)
    int rE = m0 + wm + (lane >> 2);
    int cE = n0 + wn + 2 * (lane & 3);
#pragma unroll
    for (int mm = 0; mm < 4; mm++) {
#pragma unroll
        for (int nn = 0; nn < 4; nn++) {
            float* base = g_h + (size_t)(rE + mm * 16) * 1024 + cE + nn * 8;
            *reinterpret_cast<float2*>(base) =
                make_float2(acc[mm][nn][0], acc[mm][nn][1]);
            *reinterpret_cast<float2*>(base + 8 * 1024) =
                make_float2(acc[mm][nn][2], acc[mm][nn][3]);
        }
    }
}

// ---------------------------------------------------------------------------
// BN pipeline
// ---------------------------------------------------------------------------
__global__ void zero_stats_kernel() {
    int t = threadIdx.x;
    g_sum[t] = 0.0f;
    g_sumsq[t] = 0.0f;
}

__global__ void colstats_kernel() {
    int col = threadIdx.x;                  // 1024 threads
    int r0 = blockIdx.x * 128;              // 128 blocks
    float s = 0.0f, s2 = 0.0f;
    for (int i = 0; i < 128; i++) {
        float v = g_h[(size_t)(r0 + i) * 1024 + col];
        s += v;
        s2 += v * v;
    }
    atomicAdd(&g_sum[col], s);
    atomicAdd(&g_sumsq[col], s2);
}

// BN (batch stats, biased var) + ReLU + hi/lo bf16 split (out stride 2048)
__global__ void bnrelu_kernel(const float* __restrict__ g, const float* __restrict__ b) {
    int col = blockIdx.x * 256 + threadIdx.x;   // grid.x = 4 -> 1024 cols
    const float invB = 1.0f / 16384.0f;
    float m = g_sum[col] * invB;
    float var = g_sumsq[col] * invB - m * m;
    float sc = g[col] * rsqrtf(var + 1e-5f);
    float sh = b[col] - m * sc;
    int r0 = blockIdx.y * 128;                  // grid.y = 128
    for (int i = 0; i < 128; i++) {
        size_t r = (size_t)(r0 + i);
        float v = g_h[r * 1024 + col] * sc + sh;
        v = fmaxf(v, 0.0f);
        __nv_bfloat16 hi = __float2bfloat16(v);
        __nv_bfloat16 lo = __float2bfloat16(v - __bfloat162float(hi));
        g_act[r * 2048 + col] = hi;
        g_act[r * 2048 + 1024 + col] = lo;
    }
}

// ---------------------------------------------------------------------------
// Head: out[b, j] = sigmoid( sum_k (hi+lo)[b,k] * sign(w4[j,k]) )
// ---------------------------------------------------------------------------
__global__ void head_kernel(const float* __restrict__ w4, float* __restrict__ out) {
    __shared__ float ws[10][1024];
    int tid = threadIdx.x;
    for (int i = tid; i < 10 * 1024; i += 256)
        ws[i / 1024][i % 1024] = (w4[i] >= 0.0f) ? 1.0f : -1.0f;
    __syncthreads();

    int warp = tid >> 5, lane = tid & 31;
    size_t row = (size_t)blockIdx.x * 8 + warp;     // 2048 blocks * 8 warps
    const __nv_bfloat16* a = g_act + row * 2048;

    float acc[10];
#pragma unroll
    for (int j = 0; j < 10; j++) acc[j] = 0.0f;

    for (int k = lane; k < 1024; k += 32) {
        float v = __bfloat162float(a[k]) + __bfloat162float(a[1024 + k]);
#pragma unroll
        for (int j = 0; j < 10; j++) acc[j] += v * ws[j][k];
    }
#pragma unroll
    for (int j = 0; j < 10; j++) {
#pragma unroll
        for (int o = 16; o > 0; o >>= 1)
            acc[j] += __shfl_xor_sync(0xFFFFFFFFu, acc[j], o);
    }
    if (lane == 0) {
#pragma unroll
        for (int j = 0; j < 10; j++)
            out[row * 10 + j] = 1.0f / (1.0f + __expf(-acc[j]));
    }
}

// ---------------------------------------------------------------------------
// Launch
// ---------------------------------------------------------------------------
extern "C" void kernel_launch(void* const* d_in, const int* in_sizes, int n_in,
                              void* d_out, int out_size) {
    (void)in_sizes; (void)n_in; (void)out_size;
    const float* x  = (const float*)d_in[0];
    const float* w1 = (const float*)d_in[1];
    const float* g1 = (const float*)d_in[2];
    const float* b1 = (const float*)d_in[3];
    const float* w2 = (const float*)d_in[4];
    const float* g2 = (const float*)d_in[5];
    const float* b2 = (const float*)d_in[6];
    const float* w3 = (const float*)d_in[7];
    const float* g3 = (const float*)d_in[8];
    const float* b3 = (const float*)d_in[9];
    const float* w4 = (const float*)d_in[10];
    float* out = (float*)d_out;

    cudaFuncSetAttribute(gemm_kernel, cudaFuncAttributeMaxDynamicSharedMemorySize, GEMM_SMEM);

    // input hi/lo split (pad K 1568 -> 1600)
    prep_x_kernel<<<102400, 256>>>(x);

    // layer 1: catK=1568 pad 1600 -> 25 K-tiles
    binarize_kernel<<<6400, 256>>>(w1, 784, 1600);
    gemm_kernel<<<dim3(128, 8), 256, GEMM_SMEM>>>(1600, 25);
    zero_stats_kernel<<<1, 1024>>>();
    colstats_kernel<<<128, 1024>>>();
    bnrelu_kernel<<<dim3(4, 128), 256>>>(g1, b1);

    // layer 2: catK=2048 -> 32 K-tiles
    binarize_kernel<<<8192, 256>>>(w2, 1024, 2048);
    gemm_kernel<<<dim3(128, 8), 256, GEMM_SMEM>>>(2048, 32);
    zero_stats_kernel<<<1, 1024>>>();
    colstats_kernel<<<128, 1024>>>();
    bnrelu_kernel<<<dim3(4, 128), 256>>>(g2, b2);

    // layer 3
    binarize_kernel<<<8192, 256>>>(w3, 1024, 2048);
    gemm_kernel<<<dim3(128, 8), 256, GEMM_SMEM>>>(2048, 32);
    zero_stats_kernel<<<1, 1024>>>();
    colstats_kernel<<<128, 1024>>>();
    bnrelu_kernel<<<dim3(4, 128), 256>>>(g3, b3);

    // head + sigmoid
    head_kernel<<<2048, 256>>>(w4, out);
}

// round 3
// speedup vs baseline: 1.1314x; 1.1314x over previous
#include <cuda_runtime.h>
#include <cuda_bf16.h>
#include <cstdint>

// ---------------------------------------------------------------------------
// Binarized MLP via hi/lo bf16 split (K-concatenated, sign weights duplicated)
// mma.sync.m16n8k16 GEMM, fp32 accumulate -> fp32-level accuracy.
// R2 improvements: 64x64 warp tiles (LDS-bound -> MMA-bound), L2-friendly grid
// order, BN stats fused into GEMM epilogue, layer-3 BN fused into head.
// ---------------------------------------------------------------------------

#define BATCH 16384

__device__ __align__(256) __nv_bfloat16 g_act[(size_t)BATCH * 2048];
__device__ __align__(256) __nv_bfloat16 g_wcat[(size_t)1024 * 2048];
__device__ __align__(256) float         g_h[(size_t)BATCH * 1024];
__device__ float g_sum[1024];
__device__ float g_sumsq[1024];

// ---------------------------------------------------------------------------
// PTX helpers (baseline PTX only; compute_100 target has no tcgen05)
// ---------------------------------------------------------------------------
__device__ __forceinline__ uint32_t smem_u32(const void* p) {
    uint32_t a;
    asm("{ .reg .u64 t; cvta.to.shared.u64 t, %1; cvt.u32.u64 %0, t; }"
        : "=r"(a) : "l"(p));
    return a;
}
__device__ __forceinline__ void cp16(uint32_t dst, const void* src) {
    asm volatile("cp.async.cg.shared.global [%0], [%1], 16;"
                 :: "r"(dst), "l"(src) : "memory");
}
__device__ __forceinline__ void cp_commit() {
    asm volatile("cp.async.commit_group;" ::: "memory");
}
__device__ __forceinline__ void ldmx4(uint32_t* r, uint32_t addr) {
    asm volatile("ldmatrix.sync.aligned.m8n8.x4.shared.b16 {%0,%1,%2,%3}, [%4];"
                 : "=r"(r[0]), "=r"(r[1]), "=r"(r[2]), "=r"(r[3]) : "r"(addr));
}
__device__ __forceinline__ void mma16816(float* c, const uint32_t* a, const uint32_t* b) {
    asm volatile(
        "mma.sync.aligned.m16n8k16.row.col.f32.bf16.bf16.f32 "
        "{%0,%1,%2,%3}, {%4,%5,%6,%7}, {%8,%9}, {%0,%1,%2,%3};"
        : "+f"(c[0]), "+f"(c[1]), "+f"(c[2]), "+f"(c[3])
        : "r"(a[0]), "r"(a[1]), "r"(a[2]), "r"(a[3]), "r"(b[0]), "r"(b[1]));
}

// ---------------------------------------------------------------------------
// Prep kernels
// ---------------------------------------------------------------------------
__global__ void prep_x_kernel(const float* __restrict__ x) {
    int k = blockIdx.x * 256 + threadIdx.x;          // grid (7, 16384)
    int r = blockIdx.y;
    if (k >= 1600) return;
    __nv_bfloat16 v;
    if (k < 784) {
        v = __float2bfloat16(x[(size_t)r * 784 + k]);
    } else if (k < 1568) {
        float xv = x[(size_t)r * 784 + (k - 784)];
        float hi = __bfloat162float(__float2bfloat16(xv));
        v = __float2bfloat16(xv - hi);
    } else {
        v = __float2bfloat16(0.0f);
    }
    g_act[(size_t)r * 1600 + k] = v;
}

// wcat[n,k] = wcat[n,K+k] = sign(w[n,k]); zero-pad; block(0,0) zeroes stats
__global__ void binarize_kernel(const float* __restrict__ w, int K, int stride) {
    if (blockIdx.x == 0 && blockIdx.y == 0) {
        for (int j = threadIdx.x; j < 1024; j += 256) {
            g_sum[j] = 0.0f;
            g_sumsq[j] = 0.0f;
        }
    }
    int k = blockIdx.x * 256 + threadIdx.x;          // grid (ceil(stride/256), 1024)
    int n = blockIdx.y;
    if (k >= stride) return;
    float s = 0.0f;
    if (k < 2 * K) {
        int kk = (k < K) ? k : (k - K);
        s = (w[(size_t)n * K + kk] >= 0.0f) ? 1.0f : -1.0f;
    }
    g_wcat[(size_t)n * stride + k] = __float2bfloat16(s);
}

// ---------------------------------------------------------------------------
// GEMM: g_h[16384,1024] = g_act[16384,lda] @ g_wcat[1024,lda]^T
// CTA tile 128x128x64, 4 warps (2x2), warp tile 64x64, 3-stage cp.async.
// grid = (N=8, M=128): consecutive CTAs share A rows -> L2 reuse of A.
// Epilogue: stores h and fuses column sum / sumsq atomics.
// ---------------------------------------------------------------------------
#define GEMM_SMEM (3 * 32768)

__global__ __launch_bounds__(128, 2) void gemm_kernel(int lda, int KT) {
    extern __shared__ char smem[];
    uint32_t sb = smem_u32(smem);
    int tid = threadIdx.x, lane = tid & 31, warp = tid >> 5;
    int wm = (warp & 1) * 64;
    int wn = (warp >> 1) * 64;
    int n0 = blockIdx.x * 128, m0 = blockIdx.y * 128;
    const __nv_bfloat16* A = g_act;
    const __nv_bfloat16* W = g_wcat;

    auto load_stage = [&](int s, int kt) {
        uint32_t baseA = sb + (uint32_t)s * 32768u;
        uint32_t baseB = baseA + 16384u;
        const __nv_bfloat16* Ap = A + (size_t)m0 * lda + kt * 64;
        const __nv_bfloat16* Wp = W + (size_t)n0 * lda + kt * 64;
#pragma unroll
        for (int i = 0; i < 8; i++) {
            int idx = tid + i * 128;                 // 1024 16B chunks each
            int row = idx >> 3, ck = idx & 7;
            uint32_t sw = (uint32_t)(row * 128 + ((ck ^ (row & 7)) << 4));
            cp16(baseA + sw, Ap + (size_t)row * lda + ck * 8);
            cp16(baseB + sw, Wp + (size_t)row * lda + ck * 8);
        }
        cp_commit();
    };

    load_stage(0, 0);
    load_stage(1, 1);

    float acc[4][8][4];
#pragma unroll
    for (int mm = 0; mm < 4; mm++)
#pragma unroll
        for (int nn = 0; nn < 8; nn++)
#pragma unroll
            for (int q = 0; q < 4; q++) acc[mm][nn][q] = 0.0f;

    int rA = wm + (lane & 15);                       // A ldmatrix row
    int rB = wn + ((lane >> 4) << 3) + (lane & 7);   // B ldmatrix row
    int ckA_lo = (lane >> 4);
    int ckB_lo = ((lane >> 3) & 1);

    for (int kt = 0; kt < KT; kt++) {
        if (kt == KT - 1) asm volatile("cp.async.wait_group 0;" ::: "memory");
        else              asm volatile("cp.async.wait_group 1;" ::: "memory");
        __syncthreads();
        if (kt + 2 < KT) load_stage((kt + 2) % 3, kt + 2);

        uint32_t baseA = sb + (uint32_t)(kt % 3) * 32768u;
        uint32_t baseB = baseA + 16384u;

#pragma unroll
        for (int kk = 0; kk < 4; kk++) {
            uint32_t aF[4][4], bF[8][2];
            int ckA = kk * 2 + ckA_lo;
            int ckB = kk * 2 + ckB_lo;
#pragma unroll
            for (int mm = 0; mm < 4; mm++) {
                int row = rA + mm * 16;
                ldmx4(aF[mm], baseA + row * 128 + ((ckA ^ (row & 7)) << 4));
            }
#pragma unroll
            for (int p = 0; p < 4; p++) {
                int row = rB + p * 16;
                uint32_t r[4];
                ldmx4(r, baseB + row * 128 + ((ckB ^ (row & 7)) << 4));
                bF[p * 2][0] = r[0]; bF[p * 2][1] = r[1];
                bF[p * 2 + 1][0] = r[2]; bF[p * 2 + 1][1] = r[3];
            }
#pragma unroll
            for (int mm = 0; mm < 4; mm++)
#pragma unroll
                for (int nn = 0; nn < 8; nn++)
                    mma16816(acc[mm][nn], aF[mm], bF[nn]);
        }
    }

    // Epilogue 1: registers -> g_h
    int rE = m0 + wm + (lane >> 2);
    int cE = n0 + wn + 2 * (lane & 3);
#pragma unroll
    for (int mm = 0; mm < 4; mm++) {
#pragma unroll
        for (int nn = 0; nn < 8; nn++) {
            float* base = g_h + (size_t)(rE + mm * 16) * 1024 + cE + nn * 8;
            *reinterpret_cast<float2*>(base) =
                make_float2(acc[mm][nn][0], acc[mm][nn][1]);
            *reinterpret_cast<float2*>(base + 8 * 1024) =
                make_float2(acc[mm][nn][2], acc[mm][nn][3]);
        }
    }

    // Epilogue 2: fused column sum/sumsq (this warp covers 64 rows x 64 cols)
#pragma unroll
    for (int nn = 0; nn < 8; nn++) {
        float s0 = 0.f, s1 = 0.f, q0 = 0.f, q1 = 0.f;
#pragma unroll
        for (int mm = 0; mm < 4; mm++) {
            float a0 = acc[mm][nn][0], a1 = acc[mm][nn][1];
            float a2 = acc[mm][nn][2], a3 = acc[mm][nn][3];
            s0 += a0 + a2; s1 += a1 + a3;
            q0 += a0 * a0 + a2 * a2; q1 += a1 * a1 + a3 * a3;
        }
#pragma unroll
        for (int o = 4; o <= 16; o <<= 1) {
            s0 += __shfl_xor_sync(0xFFFFFFFFu, s0, o);
            s1 += __shfl_xor_sync(0xFFFFFFFFu, s1, o);
            q0 += __shfl_xor_sync(0xFFFFFFFFu, q0, o);
            q1 += __shfl_xor_sync(0xFFFFFFFFu, q1, o);
        }
        if (lane < 4) {
            int c = cE + nn * 8;
            atomicAdd(&g_sum[c], s0);
            atomicAdd(&g_sum[c + 1], s1);
            atomicAdd(&g_sumsq[c], q0);
            atomicAdd(&g_sumsq[c + 1], q1);
        }
    }
}

// ---------------------------------------------------------------------------
// BN (batch stats, biased var) + ReLU + hi/lo bf16 split (out stride 2048)
// ---------------------------------------------------------------------------
__global__ void bnrelu_kernel(const float* __restrict__ g, const float* __restrict__ b) {
    int col = blockIdx.x * 256 + threadIdx.x;   // grid.x = 4
    const float invB = 1.0f / 16384.0f;
    float m = g_sum[col] * invB;
    float var = g_sumsq[col] * invB - m * m;
    float sc = g[col] * rsqrtf(var + 1e-5f);
    float sh = b[col] - m * sc;
    int r0 = blockIdx.y * 128;                  // grid.y = 128
    for (int i = 0; i < 128; i++) {
        size_t r = (size_t)(r0 + i);
        float v = g_h[r * 1024 + col] * sc + sh;
        v = fmaxf(v, 0.0f);
        __nv_bfloat16 hi = __float2bfloat16(v);
        __nv_bfloat16 lo = __float2bfloat16(v - __bfloat162float(hi));
        g_act[r * 2048 + col] = hi;
        g_act[r * 2048 + 1024 + col] = lo;
    }
}

// ---------------------------------------------------------------------------
// Head with fused layer-3 BN+ReLU:
// out[b,j] = sigmoid( sum_k relu(h[b,k]*sc[k]+sh[k]) * sign(w4[j,k]) )
// ---------------------------------------------------------------------------
__global__ __launch_bounds__(512) void head_kernel(
    const float* __restrict__ w4, const float* __restrict__ g,
    const float* __restrict__ b, float* __restrict__ out) {
    __shared__ float ws[10][1024];
    __shared__ float s_sc[1024], s_sh[1024];
    int tid = threadIdx.x;
    for (int i = tid; i < 10 * 1024; i += 512)
        ws[i >> 10][i & 1023] = (w4[i] >= 0.0f) ? 1.0f : -1.0f;
    const float invB = 1.0f / 16384.0f;
    for (int c = tid; c < 1024; c += 512) {
        float m = g_sum[c] * invB;
        float var = g_sumsq[c] * invB - m * m;
        float sc = g[c] * rsqrtf(var + 1e-5f);
        s_sc[c] = sc;
        s_sh[c] = b[c] - m * sc;
    }
    __syncthreads();

    int warp = tid >> 5, lane = tid & 31;
    size_t row = (size_t)blockIdx.x * 16 + warp;     // 1024 blocks * 16 warps
    const float* h = g_h + row * 1024;

    float acc[10];
#pragma unroll
    for (int j = 0; j < 10; j++) acc[j] = 0.0f;

    for (int k = lane; k < 1024; k += 32) {
        float v = fmaxf(h[k] * s_sc[k] + s_sh[k], 0.0f);
#pragma unroll
        for (int j = 0; j < 10; j++) acc[j] += v * ws[j][k];
    }
#pragma unroll
    for (int j = 0; j < 10; j++) {
#pragma unroll
        for (int o = 16; o > 0; o >>= 1)
            acc[j] += __shfl_xor_sync(0xFFFFFFFFu, acc[j], o);
    }
    if (lane == 0) {
#pragma unroll
        for (int j = 0; j < 10; j++)
            out[row * 10 + j] = 1.0f / (1.0f + __expf(-acc[j]));
    }
}

// ---------------------------------------------------------------------------
// Launch
// ---------------------------------------------------------------------------
extern "C" void kernel_launch(void* const* d_in, const int* in_sizes, int n_in,
                              void* d_out, int out_size) {
    (void)in_sizes; (void)n_in; (void)out_size;
    const float* x  = (const float*)d_in[0];
    const float* w1 = (const float*)d_in[1];
    const float* g1 = (const float*)d_in[2];
    const float* b1 = (const float*)d_in[3];
    const float* w2 = (const float*)d_in[4];
    const float* g2 = (const float*)d_in[5];
    const float* b2 = (const float*)d_in[6];
    const float* w3 = (const float*)d_in[7];
    const float* g3 = (const float*)d_in[8];
    const float* b3 = (const float*)d_in[9];
    const float* w4 = (const float*)d_in[10];
    float* out = (float*)d_out;

    cudaFuncSetAttribute(gemm_kernel, cudaFuncAttributeMaxDynamicSharedMemorySize, GEMM_SMEM);

    prep_x_kernel<<<dim3(7, 16384), 256>>>(x);

    // layer 1: catK=1568 pad 1600 -> 25 K-tiles
    binarize_kernel<<<dim3(7, 1024), 256>>>(w1, 784, 1600);
    gemm_kernel<<<dim3(8, 128), 128, GEMM_SMEM>>>(1600, 25);
    bnrelu_kernel<<<dim3(4, 128), 256>>>(g1, b1);

    // layer 2: catK=2048 -> 32 K-tiles
    binarize_kernel<<<dim3(8, 1024), 256>>>(w2, 1024, 2048);
    gemm_kernel<<<dim3(8, 128), 128, GEMM_SMEM>>>(2048, 32);
    bnrelu_kernel<<<dim3(4, 128), 256>>>(g2, b2);

    // layer 3
    binarize_kernel<<<dim3(8, 1024), 256>>>(w3, 1024, 2048);
    gemm_kernel<<<dim3(8, 128), 128, GEMM_SMEM>>>(2048, 32);

    // head: fused BN3 + ReLU + binarized dot + sigmoid
    head_kernel<<<1024, 512>>>(w4, g3, b3, out);
}

// round 5
// speedup vs baseline: 2.1420x; 1.8933x over previous
#include <cuda_runtime.h>
#include <cuda_bf16.h>
#include <cstdint>

// ---------------------------------------------------------------------------
// Binarized MLP. Weights are exactly +-1, so with activations in 16-bit fixed
// point v = s*(256*hi + lo), the GEMM h = sum v*w is EXACT in int32.
// Layer 1 (signed x): hi s8, lo s8, mma s8*s8.
// Layers 2/3 (ReLU, v>=0): q = round(v*8192) in [0,65535]; hi = q>>8 (u8),
// lo = q&255 (u8), mma u8*s8 for BOTH phases (R4 bugfix: lo was s8 before).
// ---------------------------------------------------------------------------

#define BATCH 16384
#define GEMM_SMEM (3 * 32768)

__device__ __align__(256) int8_t g_act[(size_t)BATCH * 2048];   // hi | lo halves
__device__ __align__(256) int8_t g_wcat[(size_t)1024 * 2048];   // duplicated sign w
__device__ __align__(256) float  g_h[(size_t)BATCH * 1024];     // pre-BN GEMM out
__device__ float g_sum[1024];
__device__ float g_sumsq[1024];
__device__ float g_sc[1024];
__device__ float g_sh[1024];

// ---------------------------------------------------------------------------
// PTX helpers (baseline PTX; compute_100 target has no tcgen05)
// ---------------------------------------------------------------------------
__device__ __forceinline__ uint32_t smem_u32(const void* p) {
    uint32_t a;
    asm("{ .reg .u64 t; cvta.to.shared.u64 t, %1; cvt.u32.u64 %0, t; }"
        : "=r"(a) : "l"(p));
    return a;
}
__device__ __forceinline__ void cp16(uint32_t dst, const void* src) {
    asm volatile("cp.async.cg.shared.global [%0], [%1], 16;"
                 :: "r"(dst), "l"(src) : "memory");
}
__device__ __forceinline__ void cp_commit() {
    asm volatile("cp.async.commit_group;" ::: "memory");
}
__device__ __forceinline__ void ldmx4(uint32_t* r, uint32_t addr) {
    asm volatile("ldmatrix.sync.aligned.m8n8.x4.shared.b16 {%0,%1,%2,%3}, [%4];"
                 : "=r"(r[0]), "=r"(r[1]), "=r"(r[2]), "=r"(r[3]) : "r"(addr));
}
__device__ __forceinline__ void mma_s8(int* c, const uint32_t* a, const uint32_t* b) {
    asm volatile(
        "mma.sync.aligned.m16n8k32.row.col.s32.s8.s8.s32 "
        "{%0,%1,%2,%3}, {%4,%5,%6,%7}, {%8,%9}, {%0,%1,%2,%3};"
        : "+r"(c[0]), "+r"(c[1]), "+r"(c[2]), "+r"(c[3])
        : "r"(a[0]), "r"(a[1]), "r"(a[2]), "r"(a[3]), "r"(b[0]), "r"(b[1]));
}
__device__ __forceinline__ void mma_u8(int* c, const uint32_t* a, const uint32_t* b) {
    asm volatile(
        "mma.sync.aligned.m16n8k32.row.col.s32.u8.s8.s32 "
        "{%0,%1,%2,%3}, {%4,%5,%6,%7}, {%8,%9}, {%0,%1,%2,%3};"
        : "+r"(c[0]), "+r"(c[1]), "+r"(c[2]), "+r"(c[3])
        : "r"(a[0]), "r"(a[1]), "r"(a[2]), "r"(a[3]), "r"(b[0]), "r"(b[1]));
}

// ---------------------------------------------------------------------------
// prep_x: x -> s8 hi/lo, s = 2^-12. hi cols [0,896), lo cols [896,1792).
// ---------------------------------------------------------------------------
__global__ __launch_bounds__(256) void prep_x_kernel(const float* __restrict__ x) {
    int r = blockIdx.x;
    int t = threadIdx.x;
    for (int k = t; k < 896; k += 256) {
        int8_t hv = 0, lv = 0;
        if (k < 784) {
            float xv = x[(size_t)r * 784 + k];
            int hi = __float2int_rn(xv * 16.0f);
            hi = max(-127, min(127, hi));
            int lo = __float2int_rn(xv * 4096.0f - 256.0f * hi);
            lo = max(-128, min(127, lo));
            hv = (int8_t)hi; lv = (int8_t)lo;
        }
        g_act[(size_t)r * 1792 + k] = hv;
        g_act[(size_t)r * 1792 + 896 + k] = lv;
    }
}

// wcat[n,k]: sign duplicated into both K-halves; zero-pad; block(0,0) zeroes stats
__global__ void binarize_kernel(const float* __restrict__ w, int K, int stride) {
    if (blockIdx.x == 0 && blockIdx.y == 0) {
        for (int j = threadIdx.x; j < 1024; j += 256) {
            g_sum[j] = 0.0f;
            g_sumsq[j] = 0.0f;
        }
    }
    int k = blockIdx.x * 256 + threadIdx.x;
    int n = blockIdx.y;
    if (k >= stride) return;
    int half = stride >> 1;
    int kl = (k < half) ? k : (k - half);
    int8_t s = 0;
    if (kl < K) s = (w[(size_t)n * K + kl] >= 0.0f) ? 1 : -1;
    g_wcat[(size_t)n * stride + k] = s;
}

// ---------------------------------------------------------------------------
// int8 GEMM: g_h = scale*(256*(hi@W) + lo@W), fused column stats.
// CTA 128x128, k-tile 128B, 4 warps (64x64), 3-stage cp.async.
// acc <<= 8 at kt==hiT (exact), then lo phase accumulates.
// ---------------------------------------------------------------------------
template <int UNS>
__global__ __launch_bounds__(128, 2) void gemm_s8_kernel(int lda, int KT, int hiT,
                                                         float scale) {
    extern __shared__ char smem[];
    uint32_t sb = smem_u32(smem);
    int tid = threadIdx.x, lane = tid & 31, warp = tid >> 5;
    int wm = (warp & 1) * 64;
    int wn = (warp >> 1) * 64;
    int n0 = blockIdx.x * 128, m0 = blockIdx.y * 128;
    const int8_t* A = g_act;
    const int8_t* W = g_wcat;

    auto load_stage = [&](int s, int kt) {
        uint32_t baseA = sb + (uint32_t)s * 32768u;
        uint32_t baseB = baseA + 16384u;
        const int8_t* Ap = A + (size_t)m0 * lda + kt * 128;
        const int8_t* Wp = W + (size_t)n0 * lda + kt * 128;
#pragma unroll
        for (int i = 0; i < 8; i++) {
            int idx = tid + i * 128;
            int row = idx >> 3, ck = idx & 7;
            uint32_t sw = (uint32_t)(row * 128 + ((ck ^ (row & 7)) << 4));
            cp16(baseA + sw, Ap + (size_t)row * lda + ck * 16);
            cp16(baseB + sw, Wp + (size_t)row * lda + ck * 16);
        }
        cp_commit();
    };

    load_stage(0, 0);
    load_stage(1, 1);

    int acc[4][8][4];
#pragma unroll
    for (int mm = 0; mm < 4; mm++)
#pragma unroll
        for (int nn = 0; nn < 8; nn++)
#pragma unroll
            for (int q = 0; q < 4; q++) acc[mm][nn][q] = 0;

    int rA = wm + (lane & 15);
    int rB = wn + ((lane >> 4) << 3) + (lane & 7);
    int ckA_lo = (lane >> 4);
    int ckB_lo = ((lane >> 3) & 1);

    for (int kt = 0; kt < KT; kt++) {
        if (kt == KT - 1) asm volatile("cp.async.wait_group 0;" ::: "memory");
        else              asm volatile("cp.async.wait_group 1;" ::: "memory");
        __syncthreads();
        if (kt + 2 < KT) load_stage((kt + 2) % 3, kt + 2);

        if (kt == hiT) {
#pragma unroll
            for (int mm = 0; mm < 4; mm++)
#pragma unroll
                for (int nn = 0; nn < 8; nn++)
#pragma unroll
                    for (int q = 0; q < 4; q++) acc[mm][nn][q] <<= 8;
        }

        uint32_t baseA = sb + (uint32_t)(kt % 3) * 32768u;
        uint32_t baseB = baseA + 16384u;

#pragma unroll
        for (int kk = 0; kk < 4; kk++) {
            uint32_t aF[4][4], bF[8][2];
            int ckA = kk * 2 + ckA_lo;
            int ckB = kk * 2 + ckB_lo;
#pragma unroll
            for (int mm = 0; mm < 4; mm++) {
                int row = rA + mm * 16;
                ldmx4(aF[mm], baseA + row * 128 + ((ckA ^ (row & 7)) << 4));
            }
#pragma unroll
            for (int p = 0; p < 4; p++) {
                int row = rB + p * 16;
                uint32_t r[4];
                ldmx4(r, baseB + row * 128 + ((ckB ^ (row & 7)) << 4));
                bF[p * 2][0] = r[0]; bF[p * 2][1] = r[1];
                bF[p * 2 + 1][0] = r[2]; bF[p * 2 + 1][1] = r[3];
            }
#pragma unroll
            for (int mm = 0; mm < 4; mm++)
#pragma unroll
                for (int nn = 0; nn < 8; nn++) {
                    if (UNS) mma_u8(acc[mm][nn], aF[mm], bF[nn]);
                    else     mma_s8(acc[mm][nn], aF[mm], bF[nn]);
                }
        }
    }

    // Epilogue: convert, store, fused column sum/sumsq
    int rE = m0 + wm + (lane >> 2);
    int cE = n0 + wn + 2 * (lane & 3);
    float fa[4][8][4];
#pragma unroll
    for (int mm = 0; mm < 4; mm++)
#pragma unroll
        for (int nn = 0; nn < 8; nn++) {
#pragma unroll
            for (int q = 0; q < 4; q++)
                fa[mm][nn][q] = (float)acc[mm][nn][q] * scale;
            float* base = g_h + (size_t)(rE + mm * 16) * 1024 + cE + nn * 8;
            *reinterpret_cast<float2*>(base) =
                make_float2(fa[mm][nn][0], fa[mm][nn][1]);
            *reinterpret_cast<float2*>(base + 8 * 1024) =
                make_float2(fa[mm][nn][2], fa[mm][nn][3]);
        }

#pragma unroll
    for (int nn = 0; nn < 8; nn++) {
        float s0 = 0.f, s1 = 0.f, q0 = 0.f, q1 = 0.f;
#pragma unroll
        for (int mm = 0; mm < 4; mm++) {
            float a0 = fa[mm][nn][0], a1 = fa[mm][nn][1];
            float a2 = fa[mm][nn][2], a3 = fa[mm][nn][3];
            s0 += a0 + a2; s1 += a1 + a3;
            q0 += a0 * a0 + a2 * a2; q1 += a1 * a1 + a3 * a3;
        }
#pragma unroll
        for (int o = 4; o <= 16; o <<= 1) {
            s0 += __shfl_xor_sync(0xFFFFFFFFu, s0, o);
            s1 += __shfl_xor_sync(0xFFFFFFFFu, s1, o);
            q0 += __shfl_xor_sync(0xFFFFFFFFu, q0, o);
            q1 += __shfl_xor_sync(0xFFFFFFFFu, q1, o);
        }
        if (lane < 4) {
            int c = cE + nn * 8;
            atomicAdd(&g_sum[c], s0);
            atomicAdd(&g_sum[c + 1], s1);
            atomicAdd(&g_sumsq[c], q0);
            atomicAdd(&g_sumsq[c + 1], q1);
        }
    }
}

// ---------------------------------------------------------------------------
// BN params then vectorized BN+ReLU+quantize. v >= 0, q = round(v*8192)
// in [0,65535]; hi = q>>8 (u8), lo = q&255 (u8).  [R4 fix: lo unsigned]
// ---------------------------------------------------------------------------
__global__ void bnparams_kernel(const float* __restrict__ g, const float* __restrict__ b) {
    int c = threadIdx.x;
    const float invB = 1.0f / 16384.0f;
    float m = g_sum[c] * invB;
    float var = g_sumsq[c] * invB - m * m;
    float sc = g[c] * rsqrtf(var + 1e-5f);
    g_sc[c] = sc;
    g_sh[c] = b[c] - m * sc;
}

__global__ __launch_bounds__(256) void bnq_kernel() {
    int r = blockIdx.x;
    int t = threadIdx.x;                  // 256 threads x 4 cols
    int c = t * 4;
    float4 h = *reinterpret_cast<const float4*>(g_h + (size_t)r * 1024 + c);
    float4 sc = *reinterpret_cast<const float4*>(g_sc + c);
    float4 sh = *reinterpret_cast<const float4*>(g_sh + c);
    float v[4] = { fmaxf(fmaf(h.x, sc.x, sh.x), 0.0f),
                   fmaxf(fmaf(h.y, sc.y, sh.y), 0.0f),
                   fmaxf(fmaf(h.z, sc.z, sh.z), 0.0f),
                   fmaxf(fmaf(h.w, sc.w, sh.w), 0.0f) };
    uint8_t hv[4], lv[4];
#pragma unroll
    for (int i = 0; i < 4; i++) {
        int q = __float2int_rn(v[i] * 8192.0f);
        q = min(65535, q);
        hv[i] = (uint8_t)(q >> 8);
        lv[i] = (uint8_t)(q & 255);
    }
    *reinterpret_cast<uchar4*>(g_act + (size_t)r * 2048 + c) =
        make_uchar4(hv[0], hv[1], hv[2], hv[3]);
    *reinterpret_cast<uchar4*>(g_act + (size_t)r * 2048 + 1024 + c) =
        make_uchar4(lv[0], lv[1], lv[2], lv[3]);
}

// ---------------------------------------------------------------------------
// Head with fused layer-3 BN+ReLU (pure fp32 from g_h)
// ---------------------------------------------------------------------------
__global__ __launch_bounds__(512) void head_kernel(
    const float* __restrict__ w4, const float* __restrict__ g,
    const float* __restrict__ b, float* __restrict__ out) {
    __shared__ float ws[10][1024];
    __shared__ float s_sc[1024], s_sh[1024];
    int tid = threadIdx.x;
    for (int i = tid; i < 10 * 1024; i += 512)
        ws[i >> 10][i & 1023] = (w4[i] >= 0.0f) ? 1.0f : -1.0f;
    const float invB = 1.0f / 16384.0f;
    for (int c = tid; c < 1024; c += 512) {
        float m = g_sum[c] * invB;
        float var = g_sumsq[c] * invB - m * m;
        float sc = g[c] * rsqrtf(var + 1e-5f);
        s_sc[c] = sc;
        s_sh[c] = b[c] - m * sc;
    }
    __syncthreads();

    int warp = tid >> 5, lane = tid & 31;
    size_t row = (size_t)blockIdx.x * 16 + warp;
    const float* h = g_h + row * 1024;

    float acc[10];
#pragma unroll
    for (int j = 0; j < 10; j++) acc[j] = 0.0f;

    for (int k = lane; k < 1024; k += 32) {
        float v = fmaxf(h[k] * s_sc[k] + s_sh[k], 0.0f);
#pragma unroll
        for (int j = 0; j < 10; j++) acc[j] += v * ws[j][k];
    }
#pragma unroll
    for (int j = 0; j < 10; j++) {
#pragma unroll
        for (int o = 16; o > 0; o >>= 1)
            acc[j] += __shfl_xor_sync(0xFFFFFFFFu, acc[j], o);
    }
    if (lane == 0) {
#pragma unroll
        for (int j = 0; j < 10; j++)
            out[row * 10 + j] = 1.0f / (1.0f + __expf(-acc[j]));
    }
}

// ---------------------------------------------------------------------------
// Launch
// ---------------------------------------------------------------------------
extern "C" void kernel_launch(void* const* d_in, const int* in_sizes, int n_in,
                              void* d_out, int out_size) {
    (void)in_sizes; (void)n_in; (void)out_size;
    const float* x  = (const float*)d_in[0];
    const float* w1 = (const float*)d_in[1];
    const float* g1 = (const float*)d_in[2];
    const float* b1 = (const float*)d_in[3];
    const float* w2 = (const float*)d_in[4];
    const float* g2 = (const float*)d_in[5];
    const float* b2 = (const float*)d_in[6];
    const float* w3 = (const float*)d_in[7];
    const float* g3 = (const float*)d_in[8];
    const float* b3 = (const float*)d_in[9];
    const float* w4 = (const float*)d_in[10];
    float* out = (float*)d_out;

    cudaFuncSetAttribute(gemm_s8_kernel<0>, cudaFuncAttributeMaxDynamicSharedMemorySize, GEMM_SMEM);
    cudaFuncSetAttribute(gemm_s8_kernel<1>, cudaFuncAttributeMaxDynamicSharedMemorySize, GEMM_SMEM);

    prep_x_kernel<<<16384, 256>>>(x);

    // layer 1: s8 x s8, halves of 896 (784 + pad), stride 1792, 14 k-tiles
    binarize_kernel<<<dim3(7, 1024), 256>>>(w1, 784, 1792);
    gemm_s8_kernel<0><<<dim3(8, 128), 128, GEMM_SMEM>>>(1792, 14, 7, 1.0f / 4096.0f);
    bnparams_kernel<<<1, 1024>>>(g1, b1);
    bnq_kernel<<<16384, 256>>>();

    // layer 2: u8 x s8 (hi and lo both unsigned), stride 2048, 16 k-tiles
    binarize_kernel<<<dim3(8, 1024), 256>>>(w2, 1024, 2048);
    gemm_s8_kernel<1><<<dim3(8, 128), 128, GEMM_SMEM>>>(2048, 16, 8, 1.0f / 8192.0f);
    bnparams_kernel<<<1, 1024>>>(g2, b2);
    bnq_kernel<<<16384, 256>>>();

    // layer 3
    binarize_kernel<<<dim3(8, 1024), 256>>>(w3, 1024, 2048);
    gemm_s8_kernel<1><<<dim3(8, 128), 128, GEMM_SMEM>>>(2048, 16, 8, 1.0f / 8192.0f);

    // head: fused BN3 + ReLU + binarized dot + sigmoid
    head_kernel<<<1024, 512>>>(w4, g3, b3, out);
}